// round 7
// baseline (speedup 1.0000x reference)
#include <cuda_runtime.h>
#include <cuda_bf16.h>
#include <cstdint>

// ============================================================
// GCN via bf16-split (hi+lo) warp MMA, cp.async 3-stage pipeline.
// 64x64 warp tiles (4 warps / 128 threads per CTA, CTA tile 128x128)
// to cut ldmatrix traffic per MAC (smem crossbar was co-limiting).
//   feature GEMM:  S^T[j,i] = sum_k Wt[j,k] * H[i,k]   (EPI=0)
//   adj GEMM:      H'[i,e]  = sum_k adj[i,k]* S^T[e,k] (EPI=1 relu, EPI=2 last)
// 3 MMA terms per fp32 product: hh + hl + lh  (err ~2^-18).
// ============================================================

static constexpr unsigned NE = 32u * 512u * 512u;     // 8M elems

static __device__ __nv_bfloat16 g_Xhi[NE],  g_Xlo[NE];
static __device__ __nv_bfloat16 g_Jhi[NE],  g_Jlo[NE];    // adj split
static __device__ __nv_bfloat16 g_Shi[NE],  g_Slo[NE];
static __device__ __nv_bfloat16 g_Hhi[NE],  g_Hlo[NE];
static __device__ __nv_bfloat16 g_Wthi[3u * 512u * 512u], g_Wtlo[3u * 512u * 512u];

__device__ __forceinline__ uint32_t smem_u32(const void* p) {
    uint32_t a;
    asm("{ .reg .u64 t; cvta.to.shared.u64 t, %1; cvt.u32.u64 %0, t; }"
        : "=r"(a) : "l"(p));
    return a;
}

#define LDSM_X4(r0, r1, r2, r3, addr) \
    asm volatile("ldmatrix.sync.aligned.m8n8.x4.shared.b16 {%0,%1,%2,%3}, [%4];" \
                 : "=r"(r0), "=r"(r1), "=r"(r2), "=r"(r3) : "r"(addr))

#define CP_ASYNC16(dst, src) \
    asm volatile("cp.async.cg.shared.global [%0], [%1], 16;" \
                 :: "r"(dst), "l"(src) : "memory")
#define CP_COMMIT() asm volatile("cp.async.commit_group;" ::: "memory")
#define CP_WAIT(n)  asm volatile("cp.async.wait_group %0;" :: "n"(n) : "memory")

__device__ __forceinline__ void mma16816(float* d, const uint32_t* a,
                                         uint32_t b0, uint32_t b1) {
    asm volatile(
        "mma.sync.aligned.m16n8k16.row.col.f32.bf16.bf16.f32 "
        "{%0,%1,%2,%3}, {%4,%5,%6,%7}, {%8,%9}, {%0,%1,%2,%3};"
        : "+f"(d[0]), "+f"(d[1]), "+f"(d[2]), "+f"(d[3])
        : "r"(a[0]), "r"(a[1]), "r"(a[2]), "r"(a[3]), "r"(b0), "r"(b1));
}

// smem tile: 128 rows x 32 bf16 = 64B/row, XOR swizzle on 16B chunks:
//   q' = q ^ ((row>>1)&3)   -> conflict-free ldmatrix & cp.async stores
static constexpr int TILE  = 128 * 64;           // 8KB
static constexpr int OFF_AH = 0, OFF_AL = TILE, OFF_BH = 2*TILE, OFF_BL = 3*TILE;
static constexpr int STAGE = 4 * TILE;           // 32KB
static constexpr int NSTG  = 3;
static constexpr int SMEM_BYTES = NSTG * STAGE;  // 96KB

__device__ __forceinline__ uint32_t sw_off(int row, int q) {
    return (uint32_t)row * 64u + (uint32_t)((q ^ ((row >> 1) & 3)) << 4);
}

// EPI: 0 = store hi/lo, 1 = bias+relu -> hi/lo, 2 = bias -> fp32
template <int EPI>
__global__ __launch_bounds__(128, 2)
void hgemm(const __nv_bfloat16* __restrict__ Ahi, const __nv_bfloat16* __restrict__ Alo,
           const __nv_bfloat16* __restrict__ Bhi, const __nv_bfloat16* __restrict__ Blo,
           const float* __restrict__ bias,
           float* __restrict__ Cf,
           __nv_bfloat16* __restrict__ Chi, __nv_bfloat16* __restrict__ Clo,
           long strideA, long strideB)
{
    extern __shared__ char smem[];
    const uint32_t sb = smem_u32(smem);
    const int tid  = threadIdx.x;
    const int wid  = tid >> 5;
    const int lane = tid & 31;

    const long s = 512l * 512l;
    const size_t offA = (size_t)blockIdx.z * strideA;
    const size_t offB = (size_t)blockIdx.z * strideB;

    const int rowBlock = blockIdx.y * 128;
    const int colBlock = blockIdx.x * 128;

    const int wm = (wid >> 1) * 64;    // 2 warps in M
    const int wn = (wid & 1) * 64;     // 2 warps in N

    // cp.async geometry: 4 (row, q) pairs per thread per tile (128 threads)
    const int cQ = tid & 3;
    uint32_t dOf[4];
    size_t gA[4], gB[4];
    #pragma unroll
    for (int i = 0; i < 4; ++i) {
        const int row = (tid >> 2) + i * 32;
        dOf[i] = sw_off(row, cQ);
        gA[i] = offA + (size_t)(rowBlock + row) * 512 + cQ * 8;
        gB[i] = offB + (size_t)(colBlock + row) * 512 + cQ * 8;
    }

    auto issue = [&](int c) {
        const uint32_t st = sb + (uint32_t)(c % NSTG) * STAGE;
        const int k0 = c * 32;
        #pragma unroll
        for (int i = 0; i < 4; ++i) {
            CP_ASYNC16(st + OFF_AH + dOf[i], Ahi + gA[i] + k0);
            CP_ASYNC16(st + OFF_AL + dOf[i], Alo + gA[i] + k0);
            CP_ASYNC16(st + OFF_BH + dOf[i], Bhi + gB[i] + k0);
            CP_ASYNC16(st + OFF_BL + dOf[i], Blo + gB[i] + k0);
        }
        CP_COMMIT();
    };

    // ldmatrix geometry
    const int lmRow = lane & 15;
    const int lmQ   = lane >> 4;           // 0/1; +2 for kk=1
    uint32_t aRow[4], bRow[4];
    int aXr[4], bXr[4];
    #pragma unroll
    for (int ti = 0; ti < 4; ++ti) {
        const int r = wm + ti * 16 + lmRow;
        aRow[ti] = (uint32_t)r * 64u;
        aXr[ti]  = (r >> 1) & 3;
    }
    #pragma unroll
    for (int tjj = 0; tjj < 4; ++tjj) {
        const int r = wn + tjj * 16 + lmRow;
        bRow[tjj] = (uint32_t)r * 64u;
        bXr[tjj]  = (r >> 1) & 3;
    }

    float acc[4][8][4] = {};

    issue(0);
    issue(1);

    for (int c = 0; c < 16; ++c) {
        if (c == 15) { CP_WAIT(0); } else { CP_WAIT(1); }
        __syncthreads();
        if (c + 2 < 16) issue(c + 2);

        const uint32_t st = sb + (uint32_t)(c % NSTG) * STAGE;

        #pragma unroll
        for (int kk = 0; kk < 2; ++kk) {
            const int q = lmQ + kk * 2;
            uint32_t af[4][4], bh[4][4], bl[4][4];
            #pragma unroll
            for (int tjj = 0; tjj < 4; ++tjj) {
                const uint32_t sw = (uint32_t)((q ^ bXr[tjj]) << 4);
                LDSM_X4(bh[tjj][0], bh[tjj][1], bh[tjj][2], bh[tjj][3],
                        st + OFF_BH + bRow[tjj] + sw);
                LDSM_X4(bl[tjj][0], bl[tjj][1], bl[tjj][2], bl[tjj][3],
                        st + OFF_BL + bRow[tjj] + sw);
            }
            #pragma unroll
            for (int ti = 0; ti < 4; ++ti) {
                const uint32_t sw = (uint32_t)((q ^ aXr[ti]) << 4);
                LDSM_X4(af[ti][0], af[ti][1], af[ti][2], af[ti][3],
                        st + OFF_AH + aRow[ti] + sw);
            }
            // hh
            #pragma unroll
            for (int ti = 0; ti < 4; ++ti)
                #pragma unroll
                for (int tj = 0; tj < 8; ++tj)
                    mma16816(acc[ti][tj], af[ti],
                             bh[tj >> 1][tj & 1], bh[tj >> 1][2 + (tj & 1)]);
            // hl
            #pragma unroll
            for (int ti = 0; ti < 4; ++ti)
                #pragma unroll
                for (int tj = 0; tj < 8; ++tj)
                    mma16816(acc[ti][tj], af[ti],
                             bl[tj >> 1][tj & 1], bl[tj >> 1][2 + (tj & 1)]);
            // lh (reload A-lo frags over A-hi)
            #pragma unroll
            for (int ti = 0; ti < 4; ++ti) {
                const uint32_t sw = (uint32_t)((q ^ aXr[ti]) << 4);
                LDSM_X4(af[ti][0], af[ti][1], af[ti][2], af[ti][3],
                        st + OFF_AL + aRow[ti] + sw);
            }
            #pragma unroll
            for (int ti = 0; ti < 4; ++ti)
                #pragma unroll
                for (int tj = 0; tj < 8; ++tj)
                    mma16816(acc[ti][tj], af[ti],
                             bh[tj >> 1][tj & 1], bh[tj >> 1][2 + (tj & 1)]);
        }
    }

    // epilogue
    const size_t offC = (size_t)blockIdx.z * s;
    #pragma unroll
    for (int ti = 0; ti < 4; ++ti) {
        const int m0 = rowBlock + wm + ti * 16 + (lane >> 2);
        #pragma unroll
        for (int tj = 0; tj < 8; ++tj) {
            const int n0 = colBlock + wn + tj * 8 + (lane & 3) * 2;
            float2 v0 = make_float2(acc[ti][tj][0], acc[ti][tj][1]);
            float2 v1 = make_float2(acc[ti][tj][2], acc[ti][tj][3]);
            if (EPI != 0) {
                const float bx = __ldg(bias + n0), by = __ldg(bias + n0 + 1);
                v0.x += bx; v0.y += by; v1.x += bx; v1.y += by;
                if (EPI == 1) {
                    v0.x = fmaxf(v0.x, 0.f); v0.y = fmaxf(v0.y, 0.f);
                    v1.x = fmaxf(v1.x, 0.f); v1.y = fmaxf(v1.y, 0.f);
                }
            }
            const size_t p0 = offC + (size_t)m0 * 512 + n0;
            const size_t p1 = p0 + 8 * 512;
            if (EPI == 2) {
                *(float2*)(Cf + p0) = v0;
                *(float2*)(Cf + p1) = v1;
            } else {
                __nv_bfloat162 h0 = __floats2bfloat162_rn(v0.x, v0.y);
                __nv_bfloat162 h1 = __floats2bfloat162_rn(v1.x, v1.y);
                __nv_bfloat162 l0 = __floats2bfloat162_rn(
                    v0.x - __bfloat162float(h0.x), v0.y - __bfloat162float(h0.y));
                __nv_bfloat162 l1 = __floats2bfloat162_rn(
                    v1.x - __bfloat162float(h1.x), v1.y - __bfloat162float(h1.y));
                *(uint32_t*)(Chi + p0) = *(uint32_t*)&h0;
                *(uint32_t*)(Chi + p1) = *(uint32_t*)&h1;
                *(uint32_t*)(Clo + p0) = *(uint32_t*)&l0;
                *(uint32_t*)(Clo + p1) = *(uint32_t*)&l1;
            }
        }
    }
}

// split fp32 -> bf16 hi/lo (vectorized)
__global__ __launch_bounds__(256)
void split_f32(const float* __restrict__ in,
               __nv_bfloat16* __restrict__ hi, __nv_bfloat16* __restrict__ lo,
               int n4)
{
    const int i = blockIdx.x * blockDim.x + threadIdx.x;
    if (i >= n4) return;
    float4 v = ((const float4*)in)[i];
    __nv_bfloat162 h0 = __floats2bfloat162_rn(v.x, v.y);
    __nv_bfloat162 h1 = __floats2bfloat162_rn(v.z, v.w);
    __nv_bfloat162 l0 = __floats2bfloat162_rn(v.x - __bfloat162float(h0.x),
                                              v.y - __bfloat162float(h0.y));
    __nv_bfloat162 l1 = __floats2bfloat162_rn(v.z - __bfloat162float(h1.x),
                                              v.w - __bfloat162float(h1.y));
    uint2 uh = make_uint2(*(uint32_t*)&h0, *(uint32_t*)&h1);
    uint2 ul = make_uint2(*(uint32_t*)&l0, *(uint32_t*)&l1);
    ((uint2*)hi)[i] = uh;
    ((uint2*)lo)[i] = ul;
}

// transpose 512x512 fp32 -> bf16 hi/lo (for weights)
__global__ void transpose_split512(const float* __restrict__ in,
                                   __nv_bfloat16* __restrict__ hi,
                                   __nv_bfloat16* __restrict__ lo)
{
    __shared__ float t[32][33];
    const int bx = blockIdx.x * 32, by = blockIdx.y * 32;
    const int x = threadIdx.x, y = threadIdx.y;   // 32x8
    #pragma unroll
    for (int j = 0; j < 32; j += 8)
        t[y + j][x] = in[(size_t)(by + y + j) * 512 + bx + x];
    __syncthreads();
    #pragma unroll
    for (int j = 0; j < 32; j += 8) {
        const float v = t[x][y + j];
        const size_t p = (size_t)(bx + y + j) * 512 + by + x;
        const __nv_bfloat16 h = __float2bfloat16_rn(v);
        hi[p] = h;
        lo[p] = __float2bfloat16_rn(v - __bfloat162float(h));
    }
}

extern "C" void kernel_launch(void* const* d_in, const int* in_sizes, int n_in,
                              void* d_out, int out_size)
{
    const float* X   = (const float*)d_in[0];
    const float* adj = (const float*)d_in[1];
    const float* W0  = (const float*)d_in[2];
    const float* b0  = (const float*)d_in[3];
    const float* W1  = (const float*)d_in[4];
    const float* b1  = (const float*)d_in[5];
    const float* W2  = (const float*)d_in[6];
    const float* b2  = (const float*)d_in[7];
    float* out = (float*)d_out;

    __nv_bfloat16 *Xhi, *Xlo, *Jhi, *Jlo, *Shi, *Slo, *Hhi, *Hlo, *Wthi, *Wtlo;
    cudaGetSymbolAddress((void**)&Xhi, g_Xhi);  cudaGetSymbolAddress((void**)&Xlo, g_Xlo);
    cudaGetSymbolAddress((void**)&Jhi, g_Jhi);  cudaGetSymbolAddress((void**)&Jlo, g_Jlo);
    cudaGetSymbolAddress((void**)&Shi, g_Shi);  cudaGetSymbolAddress((void**)&Slo, g_Slo);
    cudaGetSymbolAddress((void**)&Hhi, g_Hhi);  cudaGetSymbolAddress((void**)&Hlo, g_Hlo);
    cudaGetSymbolAddress((void**)&Wthi, g_Wthi); cudaGetSymbolAddress((void**)&Wtlo, g_Wtlo);

    cudaFuncSetAttribute(hgemm<0>, cudaFuncAttributeMaxDynamicSharedMemorySize, SMEM_BYTES);
    cudaFuncSetAttribute(hgemm<1>, cudaFuncAttributeMaxDynamicSharedMemorySize, SMEM_BYTES);
    cudaFuncSetAttribute(hgemm<2>, cudaFuncAttributeMaxDynamicSharedMemorySize, SMEM_BYTES);

    const long s = 512l * 512l;
    const int n4 = (int)(NE / 4);
    split_f32<<<(n4 + 255) / 256, 256>>>(X,   Xhi, Xlo, n4);
    split_f32<<<(n4 + 255) / 256, 256>>>(adj, Jhi, Jlo, n4);
    const dim3 tgrid(16, 16), tblk(32, 8);
    transpose_split512<<<tgrid, tblk>>>(W0, Wthi + 0 * s, Wtlo + 0 * s);
    transpose_split512<<<tgrid, tblk>>>(W1, Wthi + 1 * s, Wtlo + 1 * s);
    transpose_split512<<<tgrid, tblk>>>(W2, Wthi + 2 * s, Wtlo + 2 * s);

    const dim3 grid(4, 4, 32), blk(128);
    // Layer 0:  S^T = (X @ W0)^T ;  H = relu(adj @ S + b0)
    hgemm<0><<<grid, blk, SMEM_BYTES>>>(Wthi + 0*s, Wtlo + 0*s, Xhi, Xlo,
                                        nullptr, nullptr, Shi, Slo, 0, s);
    hgemm<1><<<grid, blk, SMEM_BYTES>>>(Jhi, Jlo, Shi, Slo,
                                        b0, nullptr, Hhi, Hlo, s, s);
    // Layer 1
    hgemm<0><<<grid, blk, SMEM_BYTES>>>(Wthi + 1*s, Wtlo + 1*s, Hhi, Hlo,
                                        nullptr, nullptr, Shi, Slo, 0, s);
    hgemm<1><<<grid, blk, SMEM_BYTES>>>(Jhi, Jlo, Shi, Slo,
                                        b1, nullptr, Hhi, Hlo, s, s);
    // Layer 2 (no relu, fp32 out)
    hgemm<0><<<grid, blk, SMEM_BYTES>>>(Wthi + 2*s, Wtlo + 2*s, Hhi, Hlo,
                                        nullptr, nullptr, Shi, Slo, 0, s);
    hgemm<2><<<grid, blk, SMEM_BYTES>>>(Jhi, Jlo, Shi, Slo,
                                        b2, out, nullptr, nullptr, s, s);
}

// round 8
// speedup vs baseline: 1.0115x; 1.0115x over previous
#include <cuda_runtime.h>
#include <cuda_bf16.h>
#include <cstdint>

// ============================================================
// GCN via bf16-split (hi+lo) warp MMA, cp.async 3-stage pipeline.
// 256 threads/CTA, 8 warps (2Mx4N, 64x32 warp tiles), 2 CTAs/SM
// => 16 warps/SM (4 per SMSP) for latency hiding (prior rounds all
// capped at 8 warps/SM and converged to the same ~560us).
// Pass order per k16 minimizes live fragments (<=128 regs):
//   ld Bhi,Ahi -> hh ; ld Alo -> lh ; ld Blo (over Bhi) -> hl
// ============================================================

static constexpr unsigned NE = 32u * 512u * 512u;     // 8M elems

static __device__ __nv_bfloat16 g_Xhi[NE],  g_Xlo[NE];
static __device__ __nv_bfloat16 g_Jhi[NE],  g_Jlo[NE];    // adj split
static __device__ __nv_bfloat16 g_Shi[NE],  g_Slo[NE];
static __device__ __nv_bfloat16 g_Hhi[NE],  g_Hlo[NE];
static __device__ __nv_bfloat16 g_Wthi[3u * 512u * 512u], g_Wtlo[3u * 512u * 512u];

__device__ __forceinline__ uint32_t smem_u32(const void* p) {
    uint32_t a;
    asm("{ .reg .u64 t; cvta.to.shared.u64 t, %1; cvt.u32.u64 %0, t; }"
        : "=r"(a) : "l"(p));
    return a;
}

#define LDSM_X4(r0, r1, r2, r3, addr) \
    asm volatile("ldmatrix.sync.aligned.m8n8.x4.shared.b16 {%0,%1,%2,%3}, [%4];" \
                 : "=r"(r0), "=r"(r1), "=r"(r2), "=r"(r3) : "r"(addr))

#define CP_ASYNC16(dst, src) \
    asm volatile("cp.async.cg.shared.global [%0], [%1], 16;" \
                 :: "r"(dst), "l"(src) : "memory")
#define CP_COMMIT() asm volatile("cp.async.commit_group;" ::: "memory")
#define CP_WAIT(n)  asm volatile("cp.async.wait_group %0;" :: "n"(n) : "memory")

__device__ __forceinline__ void mma16816(float* d, const uint32_t* a,
                                         uint32_t b0, uint32_t b1) {
    asm volatile(
        "mma.sync.aligned.m16n8k16.row.col.f32.bf16.bf16.f32 "
        "{%0,%1,%2,%3}, {%4,%5,%6,%7}, {%8,%9}, {%0,%1,%2,%3};"
        : "+f"(d[0]), "+f"(d[1]), "+f"(d[2]), "+f"(d[3])
        : "r"(a[0]), "r"(a[1]), "r"(a[2]), "r"(a[3]), "r"(b0), "r"(b1));
}

// smem tile: 128 rows x 32 bf16 = 64B/row, XOR swizzle on 16B chunks:
//   q' = q ^ ((row>>1)&3)   -> conflict-free ldmatrix & cp.async stores
static constexpr int TILE  = 128 * 64;           // 8KB
static constexpr int OFF_AH = 0, OFF_AL = TILE, OFF_BH = 2*TILE, OFF_BL = 3*TILE;
static constexpr int STAGE = 4 * TILE;           // 32KB
static constexpr int NSTG  = 3;
static constexpr int SMEM_BYTES = NSTG * STAGE;  // 96KB

__device__ __forceinline__ uint32_t sw_off(int row, int q) {
    return (uint32_t)row * 64u + (uint32_t)((q ^ ((row >> 1) & 3)) << 4);
}

// EPI: 0 = store hi/lo, 1 = bias+relu -> hi/lo, 2 = bias -> fp32
template <int EPI>
__global__ __launch_bounds__(256, 2)
void hgemm(const __nv_bfloat16* __restrict__ Ahi, const __nv_bfloat16* __restrict__ Alo,
           const __nv_bfloat16* __restrict__ Bhi, const __nv_bfloat16* __restrict__ Blo,
           const float* __restrict__ bias,
           float* __restrict__ Cf,
           __nv_bfloat16* __restrict__ Chi, __nv_bfloat16* __restrict__ Clo,
           long strideA, long strideB)
{
    extern __shared__ char smem[];
    const uint32_t sb = smem_u32(smem);
    const int tid  = threadIdx.x;
    const int wid  = tid >> 5;
    const int lane = tid & 31;

    const long s = 512l * 512l;
    const size_t offA = (size_t)blockIdx.z * strideA;
    const size_t offB = (size_t)blockIdx.z * strideB;

    const int rowBlock = blockIdx.y * 128;
    const int colBlock = blockIdx.x * 128;

    const int wm = (wid >> 2) * 64;    // 2 warps in M (64 rows each)
    const int wn = (wid & 3) * 32;     // 4 warps in N (32 cols each)

    // cp.async geometry: 2 (row, q) pairs per thread per tile (256 threads)
    const int cQ = tid & 3;
    uint32_t dOf[2];
    size_t gA[2], gB[2];
    #pragma unroll
    for (int i = 0; i < 2; ++i) {
        const int row = (tid >> 2) + i * 64;
        dOf[i] = sw_off(row, cQ);
        gA[i] = offA + (size_t)(rowBlock + row) * 512 + cQ * 8;
        gB[i] = offB + (size_t)(colBlock + row) * 512 + cQ * 8;
    }

    auto issue = [&](int c) {
        const uint32_t st = sb + (uint32_t)(c % NSTG) * STAGE;
        const int k0 = c * 32;
        #pragma unroll
        for (int i = 0; i < 2; ++i) {
            CP_ASYNC16(st + OFF_AH + dOf[i], Ahi + gA[i] + k0);
            CP_ASYNC16(st + OFF_AL + dOf[i], Alo + gA[i] + k0);
            CP_ASYNC16(st + OFF_BH + dOf[i], Bhi + gB[i] + k0);
            CP_ASYNC16(st + OFF_BL + dOf[i], Blo + gB[i] + k0);
        }
        CP_COMMIT();
    };

    // ldmatrix geometry
    const int lmRow = lane & 15;
    const int lmQ   = lane >> 4;           // 0/1; +2 for kk=1
    uint32_t aRow[4], bRow[2];
    int aXr[4], bXr[2];
    #pragma unroll
    for (int ti = 0; ti < 4; ++ti) {
        const int r = wm + ti * 16 + lmRow;
        aRow[ti] = (uint32_t)r * 64u;
        aXr[ti]  = (r >> 1) & 3;
    }
    #pragma unroll
    for (int tjj = 0; tjj < 2; ++tjj) {
        const int r = wn + tjj * 16 + lmRow;
        bRow[tjj] = (uint32_t)r * 64u;
        bXr[tjj]  = (r >> 1) & 3;
    }

    float acc[4][4][4] = {};

    issue(0);
    issue(1);

    for (int c = 0; c < 16; ++c) {
        if (c == 15) { CP_WAIT(0); } else { CP_WAIT(1); }
        __syncthreads();
        if (c + 2 < 16) issue(c + 2);

        const uint32_t st = sb + (uint32_t)(c % NSTG) * STAGE;

        #pragma unroll
        for (int kk = 0; kk < 2; ++kk) {
            const int q = lmQ + kk * 2;
            uint32_t af[4][4], al[4][4], bb[2][4];
            // B hi + A hi
            #pragma unroll
            for (int tjj = 0; tjj < 2; ++tjj) {
                const uint32_t sw = (uint32_t)((q ^ bXr[tjj]) << 4);
                LDSM_X4(bb[tjj][0], bb[tjj][1], bb[tjj][2], bb[tjj][3],
                        st + OFF_BH + bRow[tjj] + sw);
            }
            #pragma unroll
            for (int ti = 0; ti < 4; ++ti) {
                const uint32_t sw = (uint32_t)((q ^ aXr[ti]) << 4);
                LDSM_X4(af[ti][0], af[ti][1], af[ti][2], af[ti][3],
                        st + OFF_AH + aRow[ti] + sw);
            }
            // hh
            #pragma unroll
            for (int ti = 0; ti < 4; ++ti)
                #pragma unroll
                for (int tj = 0; tj < 4; ++tj)
                    mma16816(acc[ti][tj], af[ti],
                             bb[tj >> 1][tj & 1], bb[tj >> 1][2 + (tj & 1)]);
            // A lo, then lh (reuses B hi)
            #pragma unroll
            for (int ti = 0; ti < 4; ++ti) {
                const uint32_t sw = (uint32_t)((q ^ aXr[ti]) << 4);
                LDSM_X4(al[ti][0], al[ti][1], al[ti][2], al[ti][3],
                        st + OFF_AL + aRow[ti] + sw);
            }
            #pragma unroll
            for (int ti = 0; ti < 4; ++ti)
                #pragma unroll
                for (int tj = 0; tj < 4; ++tj)
                    mma16816(acc[ti][tj], al[ti],
                             bb[tj >> 1][tj & 1], bb[tj >> 1][2 + (tj & 1)]);
            // B lo over B hi, then hl (reuses A hi)
            #pragma unroll
            for (int tjj = 0; tjj < 2; ++tjj) {
                const uint32_t sw = (uint32_t)((q ^ bXr[tjj]) << 4);
                LDSM_X4(bb[tjj][0], bb[tjj][1], bb[tjj][2], bb[tjj][3],
                        st + OFF_BL + bRow[tjj] + sw);
            }
            #pragma unroll
            for (int ti = 0; ti < 4; ++ti)
                #pragma unroll
                for (int tj = 0; tj < 4; ++tj)
                    mma16816(acc[ti][tj], af[ti],
                             bb[tj >> 1][tj & 1], bb[tj >> 1][2 + (tj & 1)]);
        }
    }

    // epilogue
    const size_t offC = (size_t)blockIdx.z * s;
    #pragma unroll
    for (int ti = 0; ti < 4; ++ti) {
        const int m0 = rowBlock + wm + ti * 16 + (lane >> 2);
        #pragma unroll
        for (int tj = 0; tj < 4; ++tj) {
            const int n0 = colBlock + wn + tj * 8 + (lane & 3) * 2;
            float2 v0 = make_float2(acc[ti][tj][0], acc[ti][tj][1]);
            float2 v1 = make_float2(acc[ti][tj][2], acc[ti][tj][3]);
            if (EPI != 0) {
                const float bx = __ldg(bias + n0), by = __ldg(bias + n0 + 1);
                v0.x += bx; v0.y += by; v1.x += bx; v1.y += by;
                if (EPI == 1) {
                    v0.x = fmaxf(v0.x, 0.f); v0.y = fmaxf(v0.y, 0.f);
                    v1.x = fmaxf(v1.x, 0.f); v1.y = fmaxf(v1.y, 0.f);
                }
            }
            const size_t p0 = offC + (size_t)m0 * 512 + n0;
            const size_t p1 = p0 + 8 * 512;
            if (EPI == 2) {
                *(float2*)(Cf + p0) = v0;
                *(float2*)(Cf + p1) = v1;
            } else {
                __nv_bfloat162 h0 = __floats2bfloat162_rn(v0.x, v0.y);
                __nv_bfloat162 h1 = __floats2bfloat162_rn(v1.x, v1.y);
                __nv_bfloat162 l0 = __floats2bfloat162_rn(
                    v0.x - __bfloat162float(h0.x), v0.y - __bfloat162float(h0.y));
                __nv_bfloat162 l1 = __floats2bfloat162_rn(
                    v1.x - __bfloat162float(h1.x), v1.y - __bfloat162float(h1.y));
                *(uint32_t*)(Chi + p0) = *(uint32_t*)&h0;
                *(uint32_t*)(Chi + p1) = *(uint32_t*)&h1;
                *(uint32_t*)(Clo + p0) = *(uint32_t*)&l0;
                *(uint32_t*)(Clo + p1) = *(uint32_t*)&l1;
            }
        }
    }
}

// split fp32 -> bf16 hi/lo (vectorized)
__global__ __launch_bounds__(256)
void split_f32(const float* __restrict__ in,
               __nv_bfloat16* __restrict__ hi, __nv_bfloat16* __restrict__ lo,
               int n4)
{
    const int i = blockIdx.x * blockDim.x + threadIdx.x;
    if (i >= n4) return;
    float4 v = ((const float4*)in)[i];
    __nv_bfloat162 h0 = __floats2bfloat162_rn(v.x, v.y);
    __nv_bfloat162 h1 = __floats2bfloat162_rn(v.z, v.w);
    __nv_bfloat162 l0 = __floats2bfloat162_rn(v.x - __bfloat162float(h0.x),
                                              v.y - __bfloat162float(h0.y));
    __nv_bfloat162 l1 = __floats2bfloat162_rn(v.z - __bfloat162float(h1.x),
                                              v.w - __bfloat162float(h1.y));
    uint2 uh = make_uint2(*(uint32_t*)&h0, *(uint32_t*)&h1);
    uint2 ul = make_uint2(*(uint32_t*)&l0, *(uint32_t*)&l1);
    ((uint2*)hi)[i] = uh;
    ((uint2*)lo)[i] = ul;
}

// transpose 512x512 fp32 -> bf16 hi/lo (for weights)
__global__ void transpose_split512(const float* __restrict__ in,
                                   __nv_bfloat16* __restrict__ hi,
                                   __nv_bfloat16* __restrict__ lo)
{
    __shared__ float t[32][33];
    const int bx = blockIdx.x * 32, by = blockIdx.y * 32;
    const int x = threadIdx.x, y = threadIdx.y;   // 32x8
    #pragma unroll
    for (int j = 0; j < 32; j += 8)
        t[y + j][x] = in[(size_t)(by + y + j) * 512 + bx + x];
    __syncthreads();
    #pragma unroll
    for (int j = 0; j < 32; j += 8) {
        const float v = t[x][y + j];
        const size_t p = (size_t)(bx + y + j) * 512 + by + x;
        const __nv_bfloat16 h = __float2bfloat16_rn(v);
        hi[p] = h;
        lo[p] = __float2bfloat16_rn(v - __bfloat162float(h));
    }
}

extern "C" void kernel_launch(void* const* d_in, const int* in_sizes, int n_in,
                              void* d_out, int out_size)
{
    const float* X   = (const float*)d_in[0];
    const float* adj = (const float*)d_in[1];
    const float* W0  = (const float*)d_in[2];
    const float* b0  = (const float*)d_in[3];
    const float* W1  = (const float*)d_in[4];
    const float* b1  = (const float*)d_in[5];
    const float* W2  = (const float*)d_in[6];
    const float* b2  = (const float*)d_in[7];
    float* out = (float*)d_out;

    __nv_bfloat16 *Xhi, *Xlo, *Jhi, *Jlo, *Shi, *Slo, *Hhi, *Hlo, *Wthi, *Wtlo;
    cudaGetSymbolAddress((void**)&Xhi, g_Xhi);  cudaGetSymbolAddress((void**)&Xlo, g_Xlo);
    cudaGetSymbolAddress((void**)&Jhi, g_Jhi);  cudaGetSymbolAddress((void**)&Jlo, g_Jlo);
    cudaGetSymbolAddress((void**)&Shi, g_Shi);  cudaGetSymbolAddress((void**)&Slo, g_Slo);
    cudaGetSymbolAddress((void**)&Hhi, g_Hhi);  cudaGetSymbolAddress((void**)&Hlo, g_Hlo);
    cudaGetSymbolAddress((void**)&Wthi, g_Wthi); cudaGetSymbolAddress((void**)&Wtlo, g_Wtlo);

    cudaFuncSetAttribute(hgemm<0>, cudaFuncAttributeMaxDynamicSharedMemorySize, SMEM_BYTES);
    cudaFuncSetAttribute(hgemm<1>, cudaFuncAttributeMaxDynamicSharedMemorySize, SMEM_BYTES);
    cudaFuncSetAttribute(hgemm<2>, cudaFuncAttributeMaxDynamicSharedMemorySize, SMEM_BYTES);

    const long s = 512l * 512l;
    const int n4 = (int)(NE / 4);
    split_f32<<<(n4 + 255) / 256, 256>>>(X,   Xhi, Xlo, n4);
    split_f32<<<(n4 + 255) / 256, 256>>>(adj, Jhi, Jlo, n4);
    const dim3 tgrid(16, 16), tblk(32, 8);
    transpose_split512<<<tgrid, tblk>>>(W0, Wthi + 0 * s, Wtlo + 0 * s);
    transpose_split512<<<tgrid, tblk>>>(W1, Wthi + 1 * s, Wtlo + 1 * s);
    transpose_split512<<<tgrid, tblk>>>(W2, Wthi + 2 * s, Wtlo + 2 * s);

    const dim3 grid(4, 4, 32), blk(256);
    // Layer 0:  S^T = (X @ W0)^T ;  H = relu(adj @ S + b0)
    hgemm<0><<<grid, blk, SMEM_BYTES>>>(Wthi + 0*s, Wtlo + 0*s, Xhi, Xlo,
                                        nullptr, nullptr, Shi, Slo, 0, s);
    hgemm<1><<<grid, blk, SMEM_BYTES>>>(Jhi, Jlo, Shi, Slo,
                                        b0, nullptr, Hhi, Hlo, s, s);
    // Layer 1
    hgemm<0><<<grid, blk, SMEM_BYTES>>>(Wthi + 1*s, Wtlo + 1*s, Hhi, Hlo,
                                        nullptr, nullptr, Shi, Slo, 0, s);
    hgemm<1><<<grid, blk, SMEM_BYTES>>>(Jhi, Jlo, Shi, Slo,
                                        b1, nullptr, Hhi, Hlo, s, s);
    // Layer 2 (no relu, fp32 out)
    hgemm<0><<<grid, blk, SMEM_BYTES>>>(Wthi + 2*s, Wtlo + 2*s, Hhi, Hlo,
                                        nullptr, nullptr, Shi, Slo, 0, s);
    hgemm<2><<<grid, blk, SMEM_BYTES>>>(Jhi, Jlo, Shi, Slo,
                                        b2, out, nullptr, nullptr, s, s);
}